// round 1
// baseline (speedup 1.0000x reference)
#include <cuda_runtime.h>
#include <cstdint>

// ---------------- scratch (no allocs allowed) ----------------
__device__ float  g_e2[2048];
__device__ int    g_idx[65536];
__device__ double g_partial[1024];

#define FMA2(d, a, b, c) \
    asm("fma.rn.f32x2 %0, %1, %2, %3;" : "=l"(d) : "l"(a), "l"(b), "l"(c))

// ---------------- kernel 0: codebook squared norms ----------------
__global__ void e2_kernel(const float* __restrict__ cb) {
    int warp = (blockIdx.x * blockDim.x + threadIdx.x) >> 5;
    int lane = threadIdx.x & 31;
    if (warp >= 2048) return;
    const float* row = cb + (size_t)warp * 512;
    float s = 0.f;
    #pragma unroll 4
    for (int c = lane; c < 512; c += 32) { float v = row[c]; s += v * v; }
    #pragma unroll
    for (int o = 16; o; o >>= 1) s += __shfl_xor_sync(0xffffffffu, s, o);
    if (lane == 0) g_e2[warp] = s;
}

// ---------------- kernel 1: fused distance-GEMM + argmin ----------------
// Tile: M=64 pixels (one contiguous w-row chunk) x E=128 codes, K-chunks of 16.
// Thread layout: tx = t&15 owns e-pairs {2tx+32p, 2tx+32p+1}, p=0..3 (128 e);
//                ty = t>>4 owns m = 4ty..4ty+3.
__global__ __launch_bounds__(256) void argmin_kernel(
    const float* __restrict__ z, const float* __restrict__ cb) {

    __shared__ float As[16][64];     // [kc][m]
    __shared__ float Bs[16][130];    // [kc][e], pad 130 -> conflict-free STS + aligned LDS.64
    __shared__ float e2s[128];
    __shared__ float rdS[64][17];
    __shared__ int   riS[64][17];

    const int t  = threadIdx.x;
    const int tx = t & 15;
    const int ty = t >> 4;

    const int n0 = blockIdx.x * 64;           // 64 consecutive pixels, same (b,h)
    const int b  = n0 >> 12;
    const int hw = n0 & 4095;
    const float* zb = z + (size_t)b * 512 * 4096 + hw;   // + c*4096 + m

    float bd[4];
    int   bi[4];
    #pragma unroll
    for (int i = 0; i < 4; i++) { bd[i] = 3.4e38f; bi[i] = 0x7fffffff; }

    // load-index precompute
    const int a_c  = t >> 4;          // 0..15 (channel within K-chunk)
    const int a_m  = (t & 15) * 4;    // 0..60
    const int b_e  = t >> 2;          // 0..63 (code within tile, +64 on 2nd pass)
    const int b_c4 = (t & 3) * 4;     // 0..12

    for (int eBase = 0; eBase < 2048; eBase += 128) {
        if (t < 128) e2s[t] = g_e2[eBase + t];

        unsigned long long acc[4][4];
        #pragma unroll
        for (int mi = 0; mi < 4; mi++)
            #pragma unroll
            for (int p = 0; p < 4; p++) acc[mi][p] = 0ULL;

        for (int kB = 0; kB < 512; kB += 16) {
            __syncthreads();  // protect previous-iter reads (and e2s on first iter)
            // A tile: 16 channels x 64 pixels
            float4 av = *(const float4*)(zb + (size_t)(kB + a_c) * 4096 + a_m);
            *(float4*)&As[a_c][a_m] = av;
            // B tile: 128 codes x 16 channels, stored transposed [kc][e]
            #pragma unroll
            for (int it = 0; it < 2; it++) {
                int e_l = b_e + it * 64;
                float4 bv = *(const float4*)(cb + (size_t)(eBase + e_l) * 512 + kB + b_c4);
                Bs[b_c4 + 0][e_l] = bv.x;
                Bs[b_c4 + 1][e_l] = bv.y;
                Bs[b_c4 + 2][e_l] = bv.z;
                Bs[b_c4 + 3][e_l] = bv.w;
            }
            __syncthreads();

            #pragma unroll
            for (int kc = 0; kc < 16; kc++) {
                unsigned long long a2[4];
                #pragma unroll
                for (int mi = 0; mi < 4; mi++) {
                    float a = As[kc][ty * 4 + mi];
                    asm("mov.b64 %0, {%1, %1};" : "=l"(a2[mi]) : "f"(a));
                }
                unsigned long long bp[4];
                #pragma unroll
                for (int p = 0; p < 4; p++)
                    bp[p] = *(const unsigned long long*)&Bs[kc][2 * tx + 32 * p];
                #pragma unroll
                for (int mi = 0; mi < 4; mi++)
                    #pragma unroll
                    for (int p = 0; p < 4; p++)
                        FMA2(acc[mi][p], a2[mi], bp[p], acc[mi][p]);
            }
        }

        // epilogue: d = ||e||^2 - 2 * dot ; running lexicographic (d, idx) min
        #pragma unroll
        for (int mi = 0; mi < 4; mi++) {
            #pragma unroll
            for (int p = 0; p < 4; p++) {
                float fx, fy;
                asm("mov.b64 {%0, %1}, %2;" : "=f"(fx), "=f"(fy) : "l"(acc[mi][p]));
                int el = 2 * tx + 32 * p;
                float d0 = e2s[el]     - 2.0f * fx;
                float d1 = e2s[el + 1] - 2.0f * fy;
                int e0 = eBase + el;
                if (d0 < bd[mi] || (d0 == bd[mi] && e0 < bi[mi]))     { bd[mi] = d0; bi[mi] = e0; }
                if (d1 < bd[mi] || (d1 == bd[mi] && e0 + 1 < bi[mi])) { bd[mi] = d1; bi[mi] = e0 + 1; }
            }
        }
        __syncthreads();  // epilogue readers of e2s done before next tile overwrites
    }

    // cross-thread reduction: 16 partials (tx) per pixel row
    #pragma unroll
    for (int mi = 0; mi < 4; mi++) {
        rdS[ty * 4 + mi][tx] = bd[mi];
        riS[ty * 4 + mi][tx] = bi[mi];
    }
    __syncthreads();
    if (t < 64) {
        float best = rdS[t][0];
        int   bidx = riS[t][0];
        #pragma unroll
        for (int j = 1; j < 16; j++) {
            float d = rdS[t][j];
            int   i = riS[t][j];
            if (d < best || (d == best && i < bidx)) { best = d; bidx = i; }
        }
        g_idx[n0 + t] = bidx;
    }
}

// ---------------- kernel 2: gather + transposed write + loss partials ----------------
__global__ __launch_bounds__(256) void gather_kernel(
    const float* __restrict__ z, const float* __restrict__ cb,
    float* __restrict__ out) {

    __shared__ int    idxs[64];
    __shared__ double red[256];

    const int t  = threadIdx.x;
    const int n0 = blockIdx.x * 64;
    if (t < 64) idxs[t] = g_idx[n0 + t];
    __syncthreads();

    const int b  = n0 >> 12;
    const int hw = n0 & 4095;
    const size_t base = (size_t)b * 512 * 4096 + hw;

    const int m  = t & 63;
    const int c0 = t >> 6;  // 0..3
    const float* crow = cb + (size_t)idxs[m] * 512;

    double acc = 0.0;
    #pragma unroll 4
    for (int c = c0; c < 512; c += 4) {
        float q = crow[c];                         // L2-resident gather
        size_t off = base + (size_t)c * 4096 + m;  // coalesced in m
        float zv = z[off];
        out[off] = q;
        float dlt = q - zv;
        acc += (double)dlt * (double)dlt;
    }
    red[t] = acc;
    __syncthreads();
    #pragma unroll
    for (int s = 128; s; s >>= 1) {
        if (t < s) red[t] += red[t + s];
        __syncthreads();
    }
    if (t == 0) g_partial[blockIdx.x] = red[0];
}

// ---------------- kernel 3: deterministic loss finalize ----------------
__global__ void finalize_kernel(float* __restrict__ out, int out_size, int zq_elems) {
    double s = 0.0;
    for (int i = 0; i < 1024; i++) s += g_partial[i];
    double mean = s / (double)zq_elems;
    if (out_size > zq_elems) out[zq_elems] = (float)(1.25 * mean);
}

// ---------------- launch ----------------
extern "C" void kernel_launch(void* const* d_in, const int* in_sizes, int n_in,
                              void* d_out, int out_size) {
    const float* z  = (const float*)d_in[0];   // [16,512,64,64]
    const float* cb = (const float*)d_in[1];   // [2048,512]
    float* out = (float*)d_out;
    int zq_elems = in_sizes[0];                // 33554432

    e2_kernel<<<256, 256>>>(cb);
    argmin_kernel<<<1024, 256>>>(z, cb);
    gather_kernel<<<1024, 256>>>(z, cb, out);
    finalize_kernel<<<1, 1>>>(out, out_size, zq_elems);
}

// round 2
// speedup vs baseline: 1.0000x; 1.0000x over previous
#include <cuda_runtime.h>
#include <cstdint>

// ---------------- scratch (no allocs allowed) ----------------
__device__ float  g_e2[2048];
__device__ int    g_idx[65536];
__device__ double g_partial[1024];

#define FMA2(d, a, b, c) \
    asm("fma.rn.f32x2 %0, %1, %2, %3;" : "=l"(d) : "l"(a), "l"(b), "l"(c))

// ---------------- kernel 0: codebook squared norms ----------------
__global__ void e2_kernel(const float* __restrict__ cb) {
    int warp = (blockIdx.x * blockDim.x + threadIdx.x) >> 5;
    int lane = threadIdx.x & 31;
    if (warp >= 2048) return;
    const float* row = cb + (size_t)warp * 512;
    float s = 0.f;
    #pragma unroll 4
    for (int c = lane; c < 512; c += 32) { float v = row[c]; s += v * v; }
    #pragma unroll
    for (int o = 16; o; o >>= 1) s += __shfl_xor_sync(0xffffffffu, s, o);
    if (lane == 0) g_e2[warp] = s;
}

// ---------------- kernel 1: fused distance-GEMM + argmin ----------------
// Tile: M=64 pixels (one contiguous w-row chunk) x E=128 codes, K-chunks of 16.
// Thread layout: tx = t&15 owns e-pairs {2tx+32p, 2tx+32p+1}, p=0..3 (128 e);
//                ty = t>>4 owns m = 4ty..4ty+3.
__global__ __launch_bounds__(256) void argmin_kernel(
    const float* __restrict__ z, const float* __restrict__ cb) {

    __shared__ float As[16][64];     // [kc][m]
    __shared__ float Bs[16][130];    // [kc][e], pad 130 -> conflict-free STS + aligned LDS.64
    __shared__ float e2s[128];
    __shared__ float rdS[64][17];
    __shared__ int   riS[64][17];

    const int t  = threadIdx.x;
    const int tx = t & 15;
    const int ty = t >> 4;

    const int n0 = blockIdx.x * 64;           // 64 consecutive pixels, same (b,h)
    const int b  = n0 >> 12;
    const int hw = n0 & 4095;
    const float* zb = z + (size_t)b * 512 * 4096 + hw;   // + c*4096 + m

    float bd[4];
    int   bi[4];
    #pragma unroll
    for (int i = 0; i < 4; i++) { bd[i] = 3.4e38f; bi[i] = 0x7fffffff; }

    // load-index precompute
    const int a_c  = t >> 4;          // 0..15 (channel within K-chunk)
    const int a_m  = (t & 15) * 4;    // 0..60
    const int b_e  = t >> 2;          // 0..63 (code within tile, +64 on 2nd pass)
    const int b_c4 = (t & 3) * 4;     // 0..12

    for (int eBase = 0; eBase < 2048; eBase += 128) {
        if (t < 128) e2s[t] = g_e2[eBase + t];

        unsigned long long acc[4][4];
        #pragma unroll
        for (int mi = 0; mi < 4; mi++)
            #pragma unroll
            for (int p = 0; p < 4; p++) acc[mi][p] = 0ULL;

        for (int kB = 0; kB < 512; kB += 16) {
            __syncthreads();  // protect previous-iter reads (and e2s on first iter)
            // A tile: 16 channels x 64 pixels
            float4 av = *(const float4*)(zb + (size_t)(kB + a_c) * 4096 + a_m);
            *(float4*)&As[a_c][a_m] = av;
            // B tile: 128 codes x 16 channels, stored transposed [kc][e]
            #pragma unroll
            for (int it = 0; it < 2; it++) {
                int e_l = b_e + it * 64;
                float4 bv = *(const float4*)(cb + (size_t)(eBase + e_l) * 512 + kB + b_c4);
                Bs[b_c4 + 0][e_l] = bv.x;
                Bs[b_c4 + 1][e_l] = bv.y;
                Bs[b_c4 + 2][e_l] = bv.z;
                Bs[b_c4 + 3][e_l] = bv.w;
            }
            __syncthreads();

            #pragma unroll
            for (int kc = 0; kc < 16; kc++) {
                unsigned long long a2[4];
                #pragma unroll
                for (int mi = 0; mi < 4; mi++) {
                    float a = As[kc][ty * 4 + mi];
                    asm("mov.b64 %0, {%1, %1};" : "=l"(a2[mi]) : "f"(a));
                }
                unsigned long long bp[4];
                #pragma unroll
                for (int p = 0; p < 4; p++)
                    bp[p] = *(const unsigned long long*)&Bs[kc][2 * tx + 32 * p];
                #pragma unroll
                for (int mi = 0; mi < 4; mi++)
                    #pragma unroll
                    for (int p = 0; p < 4; p++)
                        FMA2(acc[mi][p], a2[mi], bp[p], acc[mi][p]);
            }
        }

        // epilogue: d = ||e||^2 - 2 * dot ; running lexicographic (d, idx) min
        #pragma unroll
        for (int mi = 0; mi < 4; mi++) {
            #pragma unroll
            for (int p = 0; p < 4; p++) {
                float fx, fy;
                asm("mov.b64 {%0, %1}, %2;" : "=f"(fx), "=f"(fy) : "l"(acc[mi][p]));
                int el = 2 * tx + 32 * p;
                float d0 = e2s[el]     - 2.0f * fx;
                float d1 = e2s[el + 1] - 2.0f * fy;
                int e0 = eBase + el;
                if (d0 < bd[mi] || (d0 == bd[mi] && e0 < bi[mi]))     { bd[mi] = d0; bi[mi] = e0; }
                if (d1 < bd[mi] || (d1 == bd[mi] && e0 + 1 < bi[mi])) { bd[mi] = d1; bi[mi] = e0 + 1; }
            }
        }
        __syncthreads();  // epilogue readers of e2s done before next tile overwrites
    }

    // cross-thread reduction: 16 partials (tx) per pixel row
    #pragma unroll
    for (int mi = 0; mi < 4; mi++) {
        rdS[ty * 4 + mi][tx] = bd[mi];
        riS[ty * 4 + mi][tx] = bi[mi];
    }
    __syncthreads();
    if (t < 64) {
        float best = rdS[t][0];
        int   bidx = riS[t][0];
        #pragma unroll
        for (int j = 1; j < 16; j++) {
            float d = rdS[t][j];
            int   i = riS[t][j];
            if (d < best || (d == best && i < bidx)) { best = d; bidx = i; }
        }
        g_idx[n0 + t] = bidx;
    }
}

// ---------------- kernel 2: gather + transposed write + loss partials ----------------
__global__ __launch_bounds__(256) void gather_kernel(
    const float* __restrict__ z, const float* __restrict__ cb,
    float* __restrict__ out) {

    __shared__ int    idxs[64];
    __shared__ double red[256];

    const int t  = threadIdx.x;
    const int n0 = blockIdx.x * 64;
    if (t < 64) idxs[t] = g_idx[n0 + t];
    __syncthreads();

    const int b  = n0 >> 12;
    const int hw = n0 & 4095;
    const size_t base = (size_t)b * 512 * 4096 + hw;

    const int m  = t & 63;
    const int c0 = t >> 6;  // 0..3
    const float* crow = cb + (size_t)idxs[m] * 512;

    double acc = 0.0;
    #pragma unroll 4
    for (int c = c0; c < 512; c += 4) {
        float q = crow[c];                         // L2-resident gather
        size_t off = base + (size_t)c * 4096 + m;  // coalesced in m
        float zv = z[off];
        out[off] = q;
        float dlt = q - zv;
        acc += (double)dlt * (double)dlt;
    }
    red[t] = acc;
    __syncthreads();
    #pragma unroll
    for (int s = 128; s; s >>= 1) {
        if (t < s) red[t] += red[t + s];
        __syncthreads();
    }
    if (t == 0) g_partial[blockIdx.x] = red[0];
}

// ---------------- kernel 3: deterministic loss finalize ----------------
__global__ void finalize_kernel(float* __restrict__ out, int out_size, int zq_elems) {
    double s = 0.0;
    for (int i = 0; i < 1024; i++) s += g_partial[i];
    double mean = s / (double)zq_elems;
    if (out_size > zq_elems) out[zq_elems] = (float)(1.25 * mean);
}

// ---------------- launch ----------------
extern "C" void kernel_launch(void* const* d_in, const int* in_sizes, int n_in,
                              void* d_out, int out_size) {
    const float* z  = (const float*)d_in[0];   // [16,512,64,64]
    const float* cb = (const float*)d_in[1];   // [2048,512]
    float* out = (float*)d_out;
    int zq_elems = in_sizes[0];                // 33554432

    e2_kernel<<<256, 256>>>(cb);
    argmin_kernel<<<1024, 256>>>(z, cb);
    gather_kernel<<<1024, 256>>>(z, cb, out);
    finalize_kernel<<<1, 1>>>(out, out_size, zq_elems);
}

// round 5
// speedup vs baseline: 1.6820x; 1.6819x over previous
#include <cuda_runtime.h>
#include <cuda_bf16.h>
#include <cstdint>
#include <cfloat>

// ------------------------------------------------------------------
// device scratch (static — no allocs allowed)
// ------------------------------------------------------------------
__device__ __nv_bfloat16 g_zhi[65536ull * 512];   // bf16(z) transposed [n][c]
__device__ float         g_zt [65536ull * 512];   // fp32 z transposed [n][c]
__device__ __nv_bfloat16 g_cbhi[2048ull * 512];   // bf16(codebook) [e][c]
__device__ float  g_e2[2048];                     // fp32 ||e||^2 (warp-tree, same as R1)
__device__ int    g_idx[65536];
__device__ int    g_cand[65536][48];
__device__ int    g_resc[65536];
__device__ int    g_nresc;
__device__ int    g_fix[65536];
__device__ int    g_nfix;
__device__ double g_partial[1024];

static constexpr float W_AMB = 1.0f;   // ambiguity window (~14 sigma of bf16 GEMM noise)

// ------------------------------------------------------------------
// PTX helpers (baseline PTX only — no tcgen05 on this toolchain target)
// ------------------------------------------------------------------
__device__ __forceinline__ uint32_t smem_u32(const void* p) {
    uint32_t a;
    asm("{ .reg .u64 t; cvta.to.shared.u64 t, %1; cvt.u32.u64 %0, t; }" : "=r"(a) : "l"(p));
    return a;
}
__device__ __forceinline__ void cp16(uint32_t dst, const void* src) {
    uint64_t g = __cvta_generic_to_global(src);
    asm volatile("cp.async.cg.shared.global [%0], [%1], 16;" :: "r"(dst), "l"(g) : "memory");
}
#define CP_COMMIT() asm volatile("cp.async.commit_group;" ::: "memory")
#define CP_WAIT(N)  asm volatile("cp.async.wait_group %0;" :: "n"(N) : "memory")

__device__ __forceinline__ uint32_t swz(uint32_t x) { return x ^ ((x >> 3) & 0x70); }

__device__ __forceinline__ void ldsm4(uint32_t& r0, uint32_t& r1, uint32_t& r2, uint32_t& r3,
                                      uint32_t addr) {
    asm volatile("ldmatrix.sync.aligned.m8n8.x4.shared.b16 {%0,%1,%2,%3}, [%4];"
                 : "=r"(r0), "=r"(r1), "=r"(r2), "=r"(r3) : "r"(addr));
}
__device__ __forceinline__ void mma16816(float& c0, float& c1, float& c2, float& c3,
                                         uint32_t a0, uint32_t a1, uint32_t a2, uint32_t a3,
                                         uint32_t b0, uint32_t b1) {
    asm volatile("mma.sync.aligned.m16n8k16.row.col.f32.bf16.bf16.f32 "
                 "{%0,%1,%2,%3}, {%4,%5,%6,%7}, {%8,%9}, {%0,%1,%2,%3};"
                 : "+f"(c0), "+f"(c1), "+f"(c2), "+f"(c3)
                 : "r"(a0), "r"(a1), "r"(a2), "r"(a3), "r"(b0), "r"(b1));
}

// top-3 insertion (slot must be compile-time for register residency)
#define INS3(S, DV, IV) do {                                                   \
    if ((DV) < td[S][2]) {                                                     \
        if ((DV) < td[S][1]) {                                                 \
            td[S][2] = td[S][1]; ti[S][2] = ti[S][1];                          \
            if ((DV) < td[S][0]) {                                             \
                td[S][1] = td[S][0]; ti[S][1] = ti[S][0];                      \
                td[S][0] = (DV);     ti[S][0] = (IV);                          \
            } else { td[S][1] = (DV); ti[S][1] = (IV); }                       \
        } else { td[S][2] = (DV); ti[S][2] = (IV); }                           \
    } } while (0)

// ------------------------------------------------------------------
// prep: codebook -> bf16 + fp32 ||e||^2 (identical arithmetic to R1) ; reset counters
// ------------------------------------------------------------------
__global__ void prep_cb_kernel(const float* __restrict__ cb) {
    if (blockIdx.x == 0 && threadIdx.x == 0) { g_nfix = 0; g_nresc = 0; }
    int warp = (blockIdx.x * blockDim.x + threadIdx.x) >> 5;
    int lane = threadIdx.x & 31;
    if (warp >= 2048) return;
    const float* row = cb + (size_t)warp * 512;
    float s = 0.f;
    #pragma unroll 4
    for (int c = lane; c < 512; c += 32) {
        float v = row[c];
        s += v * v;
        g_cbhi[(size_t)warp * 512 + c] = __float2bfloat16(v);
    }
    #pragma unroll
    for (int o = 16; o; o >>= 1) s += __shfl_xor_sync(0xffffffffu, s, o);
    if (lane == 0) g_e2[warp] = s;
}

// ------------------------------------------------------------------
// prep: z [B,C,H,W] -> transposed bf16 + fp32 planes [n][c]
// ------------------------------------------------------------------
__global__ __launch_bounds__(256) void prep_z_kernel(const float* __restrict__ z) {
    __shared__ float s[32][33];
    const int tx = threadIdx.x, ty = threadIdx.y;
    const int n0 = blockIdx.x * 32;
    const int c0 = blockIdx.y * 32;
    const int b  = n0 >> 12;
    const int hw = n0 & 4095;
    #pragma unroll
    for (int i = 0; i < 4; i++) {
        int c = c0 + ty + i * 8;
        s[ty + i * 8][tx] = z[((size_t)b * 512 + c) * 4096 + hw + tx];
    }
    __syncthreads();
    #pragma unroll
    for (int i = 0; i < 4; i++) {
        float v = s[tx][ty + i * 8];
        size_t idx = (size_t)(n0 + ty + i * 8) * 512 + c0 + tx;
        g_zhi[idx] = __float2bfloat16(v);
        g_zt[idx]  = v;
    }
}

// ------------------------------------------------------------------
// main: HMMA distance GEMM + windowed top-3 candidate tracking
// CTA: 128 pixels x 2048 codes. A resident (128KB smem), B 2-stage (16KB).
// 8 warps as 2(M) x 4(N); warp tile 64x32; chunks c = nt*8+kt (16 nt, 8 kt).
// ------------------------------------------------------------------
__global__ __launch_bounds__(256, 1) void vq_mma_kernel() {
    extern __shared__ char sm[];
    const uint32_t sA = smem_u32(sm);           // 128KB: 8 kt-tiles of [128m][128B]
    const uint32_t sB = sA + 131072u;           // 2 stages x 16KB
    float* candd = (float*)sm;                  // merge reuse: [128][48]
    int*   candi = (int*)(sm + 128 * 48 * 4);   // [128][48]

    const int t = threadIdx.x;
    const int lane = t & 31;
    const int w = t >> 5;
    const int wm = w >> 2;      // 0..1  (M)
    const int wn = w & 3;       // 0..3  (N)
    const int n0 = blockIdx.x * 128;

    // ---- A resident load (once) ----
    #pragma unroll
    for (int i = 0; i < 32; i++) {
        int U = t + 256 * i;
        int m = U >> 6, r = U & 63;             // r = kt*8 + j
        int kt = r >> 3, j = r & 7;
        cp16(sA + (uint32_t)kt * 16384u + swz((uint32_t)m * 128u + (uint32_t)j * 16u),
             g_zhi + ((size_t)(n0 + m)) * 512 + r * 8);
    }
    CP_COMMIT();

    auto loadB = [&](int c) {
        int nt = c >> 3, kt = c & 7, s = c & 1;
        #pragma unroll
        for (int i = 0; i < 4; i++) {
            int U = t + 256 * i;
            int n = U >> 3, j = U & 7;
            cp16(sB + (uint32_t)s * 16384u + swz((uint32_t)n * 128u + (uint32_t)j * 16u),
                 g_cbhi + ((size_t)(nt * 128 + n)) * 512 + kt * 64 + j * 8);
        }
    };
    loadB(0);
    CP_COMMIT();

    // persistent state
    float acc[4][4][4];
    float td[8][3];
    int   ti[8][3];
    #pragma unroll
    for (int s = 0; s < 8; s++)
        #pragma unroll
        for (int k = 0; k < 3; k++) { td[s][k] = FLT_MAX; ti[s][k] = 0x7fffffff; }

    for (int c = 0; c < 128; c++) {
        const int nt = c >> 3, kt = c & 7, s = c & 1;

        if (c + 1 < 128) { loadB(c + 1); CP_COMMIT(); CP_WAIT(1); }
        else             { CP_WAIT(0); }
        __syncthreads();

        if (kt == 0) {
            #pragma unroll
            for (int f = 0; f < 4; f++)
                #pragma unroll
                for (int g = 0; g < 4; g++)
                    #pragma unroll
                    for (int q = 0; q < 4; q++) acc[f][g][q] = 0.f;
        }

        const uint32_t aT = sA + (uint32_t)kt * 16384u;
        const uint32_t bT = sB + (uint32_t)s * 16384u;

        #pragma unroll
        for (int ks = 0; ks < 4; ks++) {
            uint32_t a[4][4], bb[2][4];
            const int am = ((lane >> 3) & 1) * 8 + (lane & 7);
            const int akb = ks * 32 + (lane >> 4) * 16;
            #pragma unroll
            for (int f = 0; f < 4; f++) {
                uint32_t off = (uint32_t)((wm * 64 + f * 16 + am) * 128 + akb);
                ldsm4(a[f][0], a[f][1], a[f][2], a[f][3], aT + swz(off));
            }
            const int bn  = (lane >> 4) * 8 + (lane & 7);
            const int bkb = ks * 32 + ((lane >> 3) & 1) * 16;
            #pragma unroll
            for (int g2 = 0; g2 < 2; g2++) {
                uint32_t off = (uint32_t)((wn * 32 + g2 * 16 + bn) * 128 + bkb);
                ldsm4(bb[g2][0], bb[g2][1], bb[g2][2], bb[g2][3], bT + swz(off));
            }
            #pragma unroll
            for (int f = 0; f < 4; f++)
                #pragma unroll
                for (int g = 0; g < 4; g++)
                    mma16816(acc[f][g][0], acc[f][g][1], acc[f][g][2], acc[f][g][3],
                             a[f][0], a[f][1], a[f][2], a[f][3],
                             bb[g >> 1][(g & 1) * 2], bb[g >> 1][(g & 1) * 2 + 1]);
        }

        if (kt == 7) {
            #pragma unroll
            for (int f = 0; f < 4; f++) {
                #pragma unroll
                for (int g = 0; g < 4; g++) {
                    int nfirst = nt * 128 + wn * 32 + g * 8 + (lane & 3) * 2;
                    float e2a = g_e2[nfirst], e2b = g_e2[nfirst + 1];
                    float d0 = e2a - 2.0f * acc[f][g][0];
                    float d1 = e2b - 2.0f * acc[f][g][1];
                    float d2 = e2a - 2.0f * acc[f][g][2];
                    float d3 = e2b - 2.0f * acc[f][g][3];
                    INS3(2 * f,     d0, nfirst);
                    INS3(2 * f,     d1, nfirst + 1);
                    INS3(2 * f + 1, d2, nfirst);
                    INS3(2 * f + 1, d3, nfirst + 1);
                }
            }
        }
        __syncthreads();
    }

    // ---- merge: 16 threads x top-3 = 48 candidates per pixel row ----
    const int tslot = wn * 4 + (lane & 3);      // 0..15
    #pragma unroll
    for (int f = 0; f < 4; f++) {
        #pragma unroll
        for (int h = 0; h < 2; h++) {
            int row = wm * 64 + f * 16 + h * 8 + (lane >> 2);
            #pragma unroll
            for (int k = 0; k < 3; k++) {
                candd[row * 48 + tslot * 3 + k] = td[2 * f + h][k];
                candi[row * 48 + tslot * 3 + k] = ti[2 * f + h][k];
            }
        }
    }
    __syncthreads();

    if (t < 128) {
        const int row = t;
        const int n = n0 + row;
        float d1 = FLT_MAX, d2 = FLT_MAX;
        int i1 = 0x7fffffff;
        #pragma unroll 4
        for (int j = 0; j < 48; j++) {
            float d = candd[row * 48 + j];
            int   id = candi[row * 48 + j];
            if (d < d1 || (d == d1 && id < i1)) { d2 = d1; d1 = d; i1 = id; }
            else if (d < d2) d2 = d;
        }
        bool flag = false;
        #pragma unroll
        for (int q = 0; q < 16; q++)
            flag |= (candd[row * 48 + q * 3 + 2] < d1 + W_AMB);
        g_idx[n] = i1;
        #pragma unroll 4
        for (int j = 0; j < 48; j++) g_cand[n][j] = candi[row * 48 + j];
        if (flag) {
            int p = atomicAdd(&g_nfix, 1);
            g_fix[p] = n;
        } else if (d2 - d1 < W_AMB) {
            int p = atomicAdd(&g_nresc, 1);
            g_resc[p] = n;
        }
    }
}

// ------------------------------------------------------------------
// rescore: exact fp32 over the 48 candidates, SEQUENTIAL k-order FMA
// (bitwise-identical arithmetic to the R1 baseline that passed)
// ------------------------------------------------------------------
__global__ __launch_bounds__(256) void rescore_kernel(const float* __restrict__ cb) {
    __shared__ float zr[8][512];
    const int lane = threadIdx.x & 31;
    const int w = threadIdx.x >> 5;
    const int total = g_nresc;
    for (int p = blockIdx.x * 8 + w; p < total; p += gridDim.x * 8) {
        const int n = g_resc[p];
        for (int i = lane; i < 128; i += 32)
            *(float4*)&zr[w][i * 4] = *(const float4*)&g_zt[(size_t)n * 512 + i * 4];
        __syncwarp();
        float best = FLT_MAX; int bid = 0x7fffffff;
        #pragma unroll
        for (int j0 = 0; j0 < 2; j0++) {
            int j = j0 * 32 + lane;
            float d = FLT_MAX; int id = 0x7fffffff;
            if (j < 48) {
                id = g_cand[n][j];
                const float* cr = cb + (size_t)id * 512;
                float dot = 0.f;
                #pragma unroll 8
                for (int c = 0; c < 512; c++) dot = fmaf(zr[w][c], cr[c], dot);
                d = g_e2[id] - 2.0f * dot;
            }
            if (d < best || (d == best && id < bid)) { best = d; bid = id; }
        }
        #pragma unroll
        for (int o = 16; o; o >>= 1) {
            float od = __shfl_xor_sync(0xffffffffu, best, o);
            int   oi = __shfl_xor_sync(0xffffffffu, bid, o);
            if (od < best || (od == best && oi < bid)) { best = od; bid = oi; }
        }
        if (lane == 0) g_idx[n] = bid;
        __syncwarp();
    }
}

// ------------------------------------------------------------------
// fixup: full re-argmin over 2048 codes, SEQUENTIAL k-order FMA (R1 numerics)
// ------------------------------------------------------------------
__global__ __launch_bounds__(256) void fixup_kernel(const float* __restrict__ cb) {
    __shared__ float zr[512];
    __shared__ float rd[256];
    __shared__ int   ri[256];
    const int tid = threadIdx.x;
    const int nf = g_nfix;

    for (int f = blockIdx.x; f < nf; f += gridDim.x) {
        const int n = g_fix[f];
        for (int c = tid; c < 512; c += 256) zr[c] = g_zt[(size_t)n * 512 + c];
        __syncthreads();

        float best = FLT_MAX; int bidx = 0x7fffffff;
        for (int e = tid; e < 2048; e += 256) {
            const float* cr = cb + (size_t)e * 512;
            float dot = 0.f;
            #pragma unroll 8
            for (int c = 0; c < 512; c++) dot = fmaf(zr[c], cr[c], dot);
            float d = g_e2[e] - 2.0f * dot;
            if (d < best || (d == best && e < bidx)) { best = d; bidx = e; }
        }
        rd[tid] = best; ri[tid] = bidx;
        __syncthreads();
        #pragma unroll
        for (int sft = 128; sft; sft >>= 1) {
            if (tid < sft) {
                float d2 = rd[tid + sft]; int i2 = ri[tid + sft];
                if (d2 < rd[tid] || (d2 == rd[tid] && i2 < ri[tid])) {
                    rd[tid] = d2; ri[tid] = i2;
                }
            }
            __syncthreads();
        }
        if (tid == 0) g_idx[n] = ri[0];
        __syncthreads();
    }
}

// ------------------------------------------------------------------
// gather + transposed write + loss partials
// ------------------------------------------------------------------
__global__ __launch_bounds__(256) void gather_kernel(
    const float* __restrict__ z, const float* __restrict__ cb,
    float* __restrict__ out) {

    __shared__ int    idxs[64];
    __shared__ double red[256];

    const int t  = threadIdx.x;
    const int n0 = blockIdx.x * 64;
    if (t < 64) idxs[t] = g_idx[n0 + t];
    __syncthreads();

    const int b  = n0 >> 12;
    const int hw = n0 & 4095;
    const size_t base = (size_t)b * 512 * 4096 + hw;

    const int m  = t & 63;
    const int c0 = t >> 6;
    const float* crow = cb + (size_t)idxs[m] * 512;

    double acc = 0.0;
    #pragma unroll 4
    for (int c = c0; c < 512; c += 4) {
        float q = crow[c];
        size_t off = base + (size_t)c * 4096 + m;
        float zv = z[off];
        out[off] = q;
        float dlt = q - zv;
        acc += (double)dlt * (double)dlt;
    }
    red[t] = acc;
    __syncthreads();
    #pragma unroll
    for (int s = 128; s; s >>= 1) {
        if (t < s) red[t] += red[t + s];
        __syncthreads();
    }
    if (t == 0) g_partial[blockIdx.x] = red[0];
}

// ------------------------------------------------------------------
// parallel loss finalize
// ------------------------------------------------------------------
__global__ __launch_bounds__(256) void finalize_kernel(
    float* __restrict__ out, int out_size, int zq_elems) {
    __shared__ double s[256];
    const int t = threadIdx.x;
    double a = 0.0;
    for (int i = t; i < 1024; i += 256) a += g_partial[i];
    s[t] = a;
    __syncthreads();
    #pragma unroll
    for (int sft = 128; sft; sft >>= 1) {
        if (t < sft) s[t] += s[t + sft];
        __syncthreads();
    }
    if (t == 0 && out_size > zq_elems)
        out[zq_elems] = (float)(1.25 * s[0] / (double)zq_elems);
}

// ------------------------------------------------------------------
// launch
// ------------------------------------------------------------------
extern "C" void kernel_launch(void* const* d_in, const int* in_sizes, int n_in,
                              void* d_out, int out_size) {
    const float* z  = (const float*)d_in[0];   // [16,512,64,64]
    const float* cb = (const float*)d_in[1];   // [2048,512]
    float* out = (float*)d_out;
    const int zq_elems = in_sizes[0];          // 33554432

    const int SMEM_MAIN = 131072 + 2 * 16384;  // A resident + 2 B stages
    cudaFuncSetAttribute(vq_mma_kernel,
                         cudaFuncAttributeMaxDynamicSharedMemorySize, SMEM_MAIN);

    prep_cb_kernel<<<256, 256>>>(cb);
    prep_z_kernel<<<dim3(2048, 16), dim3(32, 8)>>>(z);
    vq_mma_kernel<<<512, 256, SMEM_MAIN>>>();
    rescore_kernel<<<256, 256>>>(cb);
    fixup_kernel<<<64, 256>>>(cb);
    gather_kernel<<<1024, 256>>>(z, cb, out);
    finalize_kernel<<<1, 256>>>(out, out_size, zq_elems);
}

// round 6
// speedup vs baseline: 2.7831x; 1.6547x over previous
#include <cuda_runtime.h>
#include <cuda_bf16.h>
#include <cstdint>
#include <cfloat>

// ------------------------------------------------------------------
// device scratch (static — no allocs allowed)
// ------------------------------------------------------------------
__device__ __nv_bfloat16 g_zhi[65536ull * 512];   // bf16(z) transposed [n][c]
__device__ float         g_zt [65536ull * 512];   // fp32 z transposed [n][c]
__device__ __nv_bfloat16 g_cbhi[2048ull * 512];   // bf16(codebook) [e][c]
__device__ float  g_e2[2048];                     // fp32 ||e||^2 (warp-tree, same as R1)
__device__ int    g_idx[65536];
__device__ int    g_cand[65536][48];
__device__ float  g_candd[65536][48];
__device__ float  g_d1[65536];
__device__ int    g_resc[65536];
__device__ int    g_nresc;
__device__ int    g_fix[65536];
__device__ int    g_nfix;
__device__ double g_partial[1024];

static constexpr float W_AMB = 0.5f;   // ambiguity window (~7 sigma of bf16 GEMM noise)

// ------------------------------------------------------------------
// PTX helpers (baseline PTX only — no tcgen05 on this toolchain target)
// ------------------------------------------------------------------
__device__ __forceinline__ uint32_t smem_u32(const void* p) {
    uint32_t a;
    asm("{ .reg .u64 t; cvta.to.shared.u64 t, %1; cvt.u32.u64 %0, t; }" : "=r"(a) : "l"(p));
    return a;
}
__device__ __forceinline__ void cp16(uint32_t dst, const void* src) {
    uint64_t g = __cvta_generic_to_global(src);
    asm volatile("cp.async.cg.shared.global [%0], [%1], 16;" :: "r"(dst), "l"(g) : "memory");
}
#define CP_COMMIT() asm volatile("cp.async.commit_group;" ::: "memory")
#define CP_WAIT(N)  asm volatile("cp.async.wait_group %0;" :: "n"(N) : "memory")

__device__ __forceinline__ uint32_t swz(uint32_t x) { return x ^ ((x >> 3) & 0x70); }

__device__ __forceinline__ void ldsm4(uint32_t& r0, uint32_t& r1, uint32_t& r2, uint32_t& r3,
                                      uint32_t addr) {
    asm volatile("ldmatrix.sync.aligned.m8n8.x4.shared.b16 {%0,%1,%2,%3}, [%4];"
                 : "=r"(r0), "=r"(r1), "=r"(r2), "=r"(r3) : "r"(addr));
}
__device__ __forceinline__ void mma16816(float& c0, float& c1, float& c2, float& c3,
                                         uint32_t a0, uint32_t a1, uint32_t a2, uint32_t a3,
                                         uint32_t b0, uint32_t b1) {
    asm volatile("mma.sync.aligned.m16n8k16.row.col.f32.bf16.bf16.f32 "
                 "{%0,%1,%2,%3}, {%4,%5,%6,%7}, {%8,%9}, {%0,%1,%2,%3};"
                 : "+f"(c0), "+f"(c1), "+f"(c2), "+f"(c3)
                 : "r"(a0), "r"(a1), "r"(a2), "r"(a3), "r"(b0), "r"(b1));
}

// top-3 insertion (slot must be compile-time for register residency)
#define INS3(S, DV, IV) do {                                                   \
    if ((DV) < td[S][2]) {                                                     \
        if ((DV) < td[S][1]) {                                                 \
            td[S][2] = td[S][1]; ti[S][2] = ti[S][1];                          \
            if ((DV) < td[S][0]) {                                             \
                td[S][1] = td[S][0]; ti[S][1] = ti[S][0];                      \
                td[S][0] = (DV);     ti[S][0] = (IV);                          \
            } else { td[S][1] = (DV); ti[S][1] = (IV); }                       \
        } else { td[S][2] = (DV); ti[S][2] = (IV); }                           \
    } } while (0)

// ------------------------------------------------------------------
// prep: codebook -> bf16 + fp32 ||e||^2 (identical arithmetic to R1) ; reset counters
// ------------------------------------------------------------------
__global__ void prep_cb_kernel(const float* __restrict__ cb) {
    if (blockIdx.x == 0 && threadIdx.x == 0) { g_nfix = 0; g_nresc = 0; }
    int warp = (blockIdx.x * blockDim.x + threadIdx.x) >> 5;
    int lane = threadIdx.x & 31;
    if (warp >= 2048) return;
    const float* row = cb + (size_t)warp * 512;
    float s = 0.f;
    #pragma unroll 4
    for (int c = lane; c < 512; c += 32) {
        float v = row[c];
        s += v * v;
        g_cbhi[(size_t)warp * 512 + c] = __float2bfloat16(v);
    }
    #pragma unroll
    for (int o = 16; o; o >>= 1) s += __shfl_xor_sync(0xffffffffu, s, o);
    if (lane == 0) g_e2[warp] = s;
}

// ------------------------------------------------------------------
// prep: z [B,C,H,W] -> transposed bf16 + fp32 planes [n][c]
// ------------------------------------------------------------------
__global__ __launch_bounds__(256) void prep_z_kernel(const float* __restrict__ z) {
    __shared__ float s[32][33];
    const int tx = threadIdx.x, ty = threadIdx.y;
    const int n0 = blockIdx.x * 32;
    const int c0 = blockIdx.y * 32;
    const int b  = n0 >> 12;
    const int hw = n0 & 4095;
    #pragma unroll
    for (int i = 0; i < 4; i++) {
        int c = c0 + ty + i * 8;
        s[ty + i * 8][tx] = z[((size_t)b * 512 + c) * 4096 + hw + tx];
    }
    __syncthreads();
    #pragma unroll
    for (int i = 0; i < 4; i++) {
        float v = s[tx][ty + i * 8];
        size_t idx = (size_t)(n0 + ty + i * 8) * 512 + c0 + tx;
        g_zhi[idx] = __float2bfloat16(v);
        g_zt[idx]  = v;
    }
}

// ------------------------------------------------------------------
// main: HMMA distance GEMM + windowed top-3 candidate tracking
// CTA: 128 pixels x 2048 codes. A resident (128KB smem), B 2-stage (16KB).
// 8 warps as 2(M) x 4(N); warp tile 64x32; chunks c = nt*8+kt (16 nt, 8 kt).
// ------------------------------------------------------------------
__global__ __launch_bounds__(256, 1) void vq_mma_kernel() {
    extern __shared__ char sm[];
    const uint32_t sA = smem_u32(sm);           // 128KB: 8 kt-tiles of [128m][128B]
    const uint32_t sB = sA + 131072u;           // 2 stages x 16KB
    float* candd = (float*)sm;                  // merge reuse: [128][48]
    int*   candi = (int*)(sm + 128 * 48 * 4);   // [128][48]

    const int t = threadIdx.x;
    const int lane = t & 31;
    const int w = t >> 5;
    const int wm = w >> 2;      // 0..1  (M)
    const int wn = w & 3;       // 0..3  (N)
    const int n0 = blockIdx.x * 128;

    // ---- A resident load (once) ----
    #pragma unroll
    for (int i = 0; i < 32; i++) {
        int U = t + 256 * i;
        int m = U >> 6, r = U & 63;             // r = kt*8 + j
        int kt = r >> 3, j = r & 7;
        cp16(sA + (uint32_t)kt * 16384u + swz((uint32_t)m * 128u + (uint32_t)j * 16u),
             g_zhi + ((size_t)(n0 + m)) * 512 + r * 8);
    }
    CP_COMMIT();

    auto loadB = [&](int c) {
        int nt = c >> 3, kt = c & 7, s = c & 1;
        #pragma unroll
        for (int i = 0; i < 4; i++) {
            int U = t + 256 * i;
            int n = U >> 3, j = U & 7;
            cp16(sB + (uint32_t)s * 16384u + swz((uint32_t)n * 128u + (uint32_t)j * 16u),
                 g_cbhi + ((size_t)(nt * 128 + n)) * 512 + kt * 64 + j * 8);
        }
    };
    loadB(0);
    CP_COMMIT();

    // persistent state
    float acc[4][4][4];
    float td[8][3];
    int   ti[8][3];
    #pragma unroll
    for (int s = 0; s < 8; s++)
        #pragma unroll
        for (int k = 0; k < 3; k++) { td[s][k] = FLT_MAX; ti[s][k] = 0x7fffffff; }

    for (int c = 0; c < 128; c++) {
        const int nt = c >> 3, kt = c & 7, s = c & 1;

        CP_WAIT(0);
        __syncthreads();
        if (c + 1 < 128) { loadB(c + 1); CP_COMMIT(); }

        if (kt == 0) {
            #pragma unroll
            for (int f = 0; f < 4; f++)
                #pragma unroll
                for (int g = 0; g < 4; g++)
                    #pragma unroll
                    for (int q = 0; q < 4; q++) acc[f][g][q] = 0.f;
        }

        const uint32_t aT = sA + (uint32_t)kt * 16384u;
        const uint32_t bT = sB + (uint32_t)s * 16384u;

        #pragma unroll
        for (int ks = 0; ks < 4; ks++) {
            uint32_t a[4][4], bb[2][4];
            const int am = ((lane >> 3) & 1) * 8 + (lane & 7);
            const int akb = ks * 32 + (lane >> 4) * 16;
            #pragma unroll
            for (int f = 0; f < 4; f++) {
                uint32_t off = (uint32_t)((wm * 64 + f * 16 + am) * 128 + akb);
                ldsm4(a[f][0], a[f][1], a[f][2], a[f][3], aT + swz(off));
            }
            const int bn  = (lane >> 4) * 8 + (lane & 7);
            const int bkb = ks * 32 + ((lane >> 3) & 1) * 16;
            #pragma unroll
            for (int g2 = 0; g2 < 2; g2++) {
                uint32_t off = (uint32_t)((wn * 32 + g2 * 16 + bn) * 128 + bkb);
                ldsm4(bb[g2][0], bb[g2][1], bb[g2][2], bb[g2][3], bT + swz(off));
            }
            #pragma unroll
            for (int f = 0; f < 4; f++)
                #pragma unroll
                for (int g = 0; g < 4; g++)
                    mma16816(acc[f][g][0], acc[f][g][1], acc[f][g][2], acc[f][g][3],
                             a[f][0], a[f][1], a[f][2], a[f][3],
                             bb[g >> 1][(g & 1) * 2], bb[g >> 1][(g & 1) * 2 + 1]);
        }

        if (kt == 7) {
            #pragma unroll
            for (int f = 0; f < 4; f++) {
                #pragma unroll
                for (int g = 0; g < 4; g++) {
                    int nfirst = nt * 128 + wn * 32 + g * 8 + (lane & 3) * 2;
                    float e2a = g_e2[nfirst], e2b = g_e2[nfirst + 1];
                    float d0 = e2a - 2.0f * acc[f][g][0];
                    float d1 = e2b - 2.0f * acc[f][g][1];
                    float d2 = e2a - 2.0f * acc[f][g][2];
                    float d3 = e2b - 2.0f * acc[f][g][3];
                    INS3(2 * f,     d0, nfirst);
                    INS3(2 * f,     d1, nfirst + 1);
                    INS3(2 * f + 1, d2, nfirst);
                    INS3(2 * f + 1, d3, nfirst + 1);
                }
            }
        }
    }
    __syncthreads();   // all warps done reading sA/sB before candd/candi alias them

    // ---- merge: 16 threads x top-3 = 48 candidates per pixel row ----
    const int tslot = wn * 4 + (lane & 3);      // 0..15
    #pragma unroll
    for (int f = 0; f < 4; f++) {
        #pragma unroll
        for (int h = 0; h < 2; h++) {
            int row = wm * 64 + f * 16 + h * 8 + (lane >> 2);
            #pragma unroll
            for (int k = 0; k < 3; k++) {
                candd[row * 48 + tslot * 3 + k] = td[2 * f + h][k];
                candi[row * 48 + tslot * 3 + k] = ti[2 * f + h][k];
            }
        }
    }
    __syncthreads();

    if (t < 128) {
        const int row = t;
        const int n = n0 + row;
        float d1 = FLT_MAX, d2 = FLT_MAX;
        int i1 = 0x7fffffff;
        #pragma unroll 4
        for (int j = 0; j < 48; j++) {
            float d = candd[row * 48 + j];
            int   id = candi[row * 48 + j];
            if (d < d1 || (d == d1 && id < i1)) { d2 = d1; d1 = d; i1 = id; }
            else if (d < d2) d2 = d;
        }
        bool flag = false;
        #pragma unroll
        for (int q = 0; q < 16; q++)
            flag |= (candd[row * 48 + q * 3 + 2] < d1 + W_AMB);
        g_idx[n] = i1;
        g_d1[n] = d1;
        #pragma unroll 4
        for (int j = 0; j < 48; j++) {
            g_cand[n][j]  = candi[row * 48 + j];
            g_candd[n][j] = candd[row * 48 + j];
        }
        if (flag) {
            int p = atomicAdd(&g_nfix, 1);
            g_fix[p] = n;
        } else if (d2 - d1 < W_AMB) {
            int p = atomicAdd(&g_nresc, 1);
            g_resc[p] = n;
        }
    }
}

// ------------------------------------------------------------------
// rescore: exact fp32 over ONLY the in-window candidates, SEQUENTIAL
// k-order FMA (bitwise-identical arithmetic to the R1 baseline)
// ------------------------------------------------------------------
__global__ __launch_bounds__(256) void rescore_kernel(const float* __restrict__ cb) {
    __shared__ float zr[8][512];
    const int lane = threadIdx.x & 31;
    const int w = threadIdx.x >> 5;
    const int total = g_nresc;
    for (int p = blockIdx.x * 8 + w; p < total; p += gridDim.x * 8) {
        const int n = g_resc[p];
        const float thr = g_d1[n] + W_AMB;
        for (int i = lane; i < 128; i += 32)
            *(float4*)&zr[w][i * 4] = *(const float4*)&g_zt[(size_t)n * 512 + i * 4];
        __syncwarp();
        float best = FLT_MAX; int bid = 0x7fffffff;
        #pragma unroll
        for (int j0 = 0; j0 < 2; j0++) {
            int j = j0 * 32 + lane;
            float d = FLT_MAX; int id = 0x7fffffff;
            if (j < 48 && g_candd[n][j] < thr) {
                id = g_cand[n][j];
                const float4* cr4 = (const float4*)(cb + (size_t)id * 512);
                float dot = 0.f;
                #pragma unroll 4
                for (int c4 = 0; c4 < 128; c4++) {
                    float4 v = cr4[c4];
                    dot = fmaf(zr[w][c4 * 4 + 0], v.x, dot);
                    dot = fmaf(zr[w][c4 * 4 + 1], v.y, dot);
                    dot = fmaf(zr[w][c4 * 4 + 2], v.z, dot);
                    dot = fmaf(zr[w][c4 * 4 + 3], v.w, dot);
                }
                d = g_e2[id] - 2.0f * dot;
            }
            if (d < best || (d == best && id < bid)) { best = d; bid = id; }
        }
        #pragma unroll
        for (int o = 16; o; o >>= 1) {
            float od = __shfl_xor_sync(0xffffffffu, best, o);
            int   oi = __shfl_xor_sync(0xffffffffu, bid, o);
            if (od < best || (od == best && oi < bid)) { best = od; bid = oi; }
        }
        if (lane == 0) g_idx[n] = bid;
        __syncwarp();
    }
}

// ------------------------------------------------------------------
// fixup: full re-argmin over 2048 codes, SEQUENTIAL k-order FMA (R1 numerics)
// ------------------------------------------------------------------
__global__ __launch_bounds__(256) void fixup_kernel(const float* __restrict__ cb) {
    __shared__ float zr[512];
    __shared__ float rd[256];
    __shared__ int   ri[256];
    const int tid = threadIdx.x;
    const int nf = g_nfix;

    for (int f = blockIdx.x; f < nf; f += gridDim.x) {
        const int n = g_fix[f];
        for (int c = tid; c < 128; c += 256)
            *(float4*)&zr[c * 4] = *(const float4*)&g_zt[(size_t)n * 512 + c * 4];
        __syncthreads();

        float best = FLT_MAX; int bidx = 0x7fffffff;
        for (int e = tid; e < 2048; e += 256) {
            const float4* cr4 = (const float4*)(cb + (size_t)e * 512);
            float dot = 0.f;
            #pragma unroll 4
            for (int c4 = 0; c4 < 128; c4++) {
                float4 v = cr4[c4];
                dot = fmaf(zr[c4 * 4 + 0], v.x, dot);
                dot = fmaf(zr[c4 * 4 + 1], v.y, dot);
                dot = fmaf(zr[c4 * 4 + 2], v.z, dot);
                dot = fmaf(zr[c4 * 4 + 3], v.w, dot);
            }
            float d = g_e2[e] - 2.0f * dot;
            if (d < best || (d == best && e < bidx)) { best = d; bidx = e; }
        }
        rd[tid] = best; ri[tid] = bidx;
        __syncthreads();
        #pragma unroll
        for (int sft = 128; sft; sft >>= 1) {
            if (tid < sft) {
                float d2 = rd[tid + sft]; int i2 = ri[tid + sft];
                if (d2 < rd[tid] || (d2 == rd[tid] && i2 < ri[tid])) {
                    rd[tid] = d2; ri[tid] = i2;
                }
            }
            __syncthreads();
        }
        if (tid == 0) g_idx[n] = ri[0];
        __syncthreads();
    }
}

// ------------------------------------------------------------------
// gather + transposed write + loss partials
// ------------------------------------------------------------------
__global__ __launch_bounds__(256) void gather_kernel(
    const float* __restrict__ z, const float* __restrict__ cb,
    float* __restrict__ out) {

    __shared__ int    idxs[64];
    __shared__ double red[256];

    const int t  = threadIdx.x;
    const int n0 = blockIdx.x * 64;
    if (t < 64) idxs[t] = g_idx[n0 + t];
    __syncthreads();

    const int b  = n0 >> 12;
    const int hw = n0 & 4095;
    const size_t base = (size_t)b * 512 * 4096 + hw;

    const int m  = t & 63;
    const int c0 = t >> 6;
    const float* crow = cb + (size_t)idxs[m] * 512;

    double acc = 0.0;
    #pragma unroll 4
    for (int c = c0; c < 512; c += 4) {
        float q = crow[c];
        size_t off = base + (size_t)c * 4096 + m;
        float zv = z[off];
        out[off] = q;
        float dlt = q - zv;
        acc += (double)dlt * (double)dlt;
    }
    red[t] = acc;
    __syncthreads();
    #pragma unroll
    for (int s = 128; s; s >>= 1) {
        if (t < s) red[t] += red[t + s];
        __syncthreads();
    }
    if (t == 0) g_partial[blockIdx.x] = red[0];
}

// ------------------------------------------------------------------
// parallel loss finalize
// ------------------------------------------------------------------
__global__ __launch_bounds__(256) void finalize_kernel(
    float* __restrict__ out, int out_size, int zq_elems) {
    __shared__ double s[256];
    const int t = threadIdx.x;
    double a = 0.0;
    for (int i = t; i < 1024; i += 256) a += g_partial[i];
    s[t] = a;
    __syncthreads();
    #pragma unroll
    for (int sft = 128; sft; sft >>= 1) {
        if (t < sft) s[t] += s[t + sft];
        __syncthreads();
    }
    if (t == 0 && out_size > zq_elems)
        out[zq_elems] = (float)(1.25 * s[0] / (double)zq_elems);
}

// ------------------------------------------------------------------
// launch
// ------------------------------------------------------------------
extern "C" void kernel_launch(void* const* d_in, const int* in_sizes, int n_in,
                              void* d_out, int out_size) {
    const float* z  = (const float*)d_in[0];   // [16,512,64,64]
    const float* cb = (const float*)d_in[1];   // [2048,512]
    float* out = (float*)d_out;
    const int zq_elems = in_sizes[0];          // 33554432

    const int SMEM_MAIN = 131072 + 2 * 16384;  // A resident + 2 B stages
    cudaFuncSetAttribute(vq_mma_kernel,
                         cudaFuncAttributeMaxDynamicSharedMemorySize, SMEM_MAIN);

    prep_cb_kernel<<<256, 256>>>(cb);
    prep_z_kernel<<<dim3(2048, 16), dim3(32, 8)>>>(z);
    vq_mma_kernel<<<512, 256, SMEM_MAIN>>>();
    rescore_kernel<<<512, 256>>>(cb);
    fixup_kernel<<<128, 256>>>(cb);
    gather_kernel<<<1024, 256>>>(z, cb, out);
    finalize_kernel<<<1, 256>>>(out, out_size, zq_elems);
}

// round 7
// speedup vs baseline: 2.8710x; 1.0316x over previous
#include <cuda_runtime.h>
#include <cuda_bf16.h>
#include <cstdint>
#include <cfloat>

// ------------------------------------------------------------------
// device scratch (static — no allocs allowed)
// ------------------------------------------------------------------
__device__ __nv_bfloat16 g_zhi[65536ull * 512];   // bf16(z) transposed [n][c]
__device__ float         g_zt [65536ull * 512];   // fp32 z transposed [n][c]
__device__ __nv_bfloat16 g_cbhi[2048ull * 512];   // bf16(codebook) [e][c]
__device__ float  g_e2[2048];                     // fp32 ||e||^2 (warp-tree, same as R1)
__device__ int    g_idx[65536];
__device__ int    g_cand[65536][48];
__device__ float  g_candd[65536][48];
__device__ float  g_d1[65536];
__device__ int    g_resc[65536];
__device__ int    g_nresc;
__device__ int    g_fix[65536];
__device__ int    g_nfix;
__device__ double g_partial[1024];

static constexpr float W_AMB = 0.5f;   // ambiguity window (~7 sigma of bf16 GEMM noise)

// ------------------------------------------------------------------
// PTX helpers (baseline PTX only — no tcgen05 on this toolchain target)
// ------------------------------------------------------------------
__device__ __forceinline__ uint32_t smem_u32(const void* p) {
    uint32_t a;
    asm("{ .reg .u64 t; cvta.to.shared.u64 t, %1; cvt.u32.u64 %0, t; }" : "=r"(a) : "l"(p));
    return a;
}
__device__ __forceinline__ void cp16(uint32_t dst, const void* src) {
    uint64_t g = __cvta_generic_to_global(src);
    asm volatile("cp.async.cg.shared.global [%0], [%1], 16;" :: "r"(dst), "l"(g) : "memory");
}
#define CP_COMMIT() asm volatile("cp.async.commit_group;" ::: "memory")
#define CP_WAIT(N)  asm volatile("cp.async.wait_group %0;" :: "n"(N) : "memory")

__device__ __forceinline__ uint32_t swz(uint32_t x) { return x ^ ((x >> 3) & 0x70); }

__device__ __forceinline__ void ldsm4(uint32_t& r0, uint32_t& r1, uint32_t& r2, uint32_t& r3,
                                      uint32_t addr) {
    asm volatile("ldmatrix.sync.aligned.m8n8.x4.shared.b16 {%0,%1,%2,%3}, [%4];"
                 : "=r"(r0), "=r"(r1), "=r"(r2), "=r"(r3) : "r"(addr));
}
__device__ __forceinline__ void mma16816(float& c0, float& c1, float& c2, float& c3,
                                         uint32_t a0, uint32_t a1, uint32_t a2, uint32_t a3,
                                         uint32_t b0, uint32_t b1) {
    asm volatile("mma.sync.aligned.m16n8k16.row.col.f32.bf16.bf16.f32 "
                 "{%0,%1,%2,%3}, {%4,%5,%6,%7}, {%8,%9}, {%0,%1,%2,%3};"
                 : "+f"(c0), "+f"(c1), "+f"(c2), "+f"(c3)
                 : "r"(a0), "r"(a1), "r"(a2), "r"(a3), "r"(b0), "r"(b1));
}

// top-3 insertion (slot must be compile-time for register residency)
#define INS3(S, DV, IV) do {                                                   \
    if ((DV) < td[S][2]) {                                                     \
        if ((DV) < td[S][1]) {                                                 \
            td[S][2] = td[S][1]; ti[S][2] = ti[S][1];                          \
            if ((DV) < td[S][0]) {                                             \
                td[S][1] = td[S][0]; ti[S][1] = ti[S][0];                      \
                td[S][0] = (DV);     ti[S][0] = (IV);                          \
            } else { td[S][1] = (DV); ti[S][1] = (IV); }                       \
        } else { td[S][2] = (DV); ti[S][2] = (IV); }                           \
    } } while (0)

// ------------------------------------------------------------------
// prep: codebook -> bf16 + fp32 ||e||^2 (identical arithmetic to R1) ; reset counters
// ------------------------------------------------------------------
__global__ void prep_cb_kernel(const float* __restrict__ cb) {
    if (blockIdx.x == 0 && threadIdx.x == 0) { g_nfix = 0; g_nresc = 0; }
    int warp = (blockIdx.x * blockDim.x + threadIdx.x) >> 5;
    int lane = threadIdx.x & 31;
    if (warp >= 2048) return;
    const float* row = cb + (size_t)warp * 512;
    float s = 0.f;
    #pragma unroll 4
    for (int c = lane; c < 512; c += 32) {
        float v = row[c];
        s += v * v;
        g_cbhi[(size_t)warp * 512 + c] = __float2bfloat16(v);
    }
    #pragma unroll
    for (int o = 16; o; o >>= 1) s += __shfl_xor_sync(0xffffffffu, s, o);
    if (lane == 0) g_e2[warp] = s;
}

// ------------------------------------------------------------------
// prep: z [B,C,H,W] -> transposed bf16 + fp32 planes [n][c]
// ------------------------------------------------------------------
__global__ __launch_bounds__(256) void prep_z_kernel(const float* __restrict__ z) {
    __shared__ float s[32][33];
    const int tx = threadIdx.x, ty = threadIdx.y;
    const int n0 = blockIdx.x * 32;
    const int c0 = blockIdx.y * 32;
    const int b  = n0 >> 12;
    const int hw = n0 & 4095;
    #pragma unroll
    for (int i = 0; i < 4; i++) {
        int c = c0 + ty + i * 8;
        s[ty + i * 8][tx] = z[((size_t)b * 512 + c) * 4096 + hw + tx];
    }
    __syncthreads();
    #pragma unroll
    for (int i = 0; i < 4; i++) {
        float v = s[tx][ty + i * 8];
        size_t idx = (size_t)(n0 + ty + i * 8) * 512 + c0 + tx;
        g_zhi[idx] = __float2bfloat16(v);
        g_zt[idx]  = v;
    }
}

// ------------------------------------------------------------------
// main: HMMA distance GEMM + windowed top-3 candidate tracking
// CTA: 128 pixels x 2048 codes, 512 threads (16 warps, 4 per SMSP).
// Warps as 4(M) x 4(N); warp tile 32x32. A resident (128KB), B 2-stage (16KB).
// chunks c = nt*8+kt (16 nt, 8 kt).
// ------------------------------------------------------------------
__global__ __launch_bounds__(512, 1) void vq_mma_kernel() {
    extern __shared__ char sm[];
    const uint32_t sA = smem_u32(sm);           // 128KB: 8 kt-tiles of [128m][128B]
    const uint32_t sB = sA + 131072u;           // 2 stages x 16KB
    float* candd = (float*)sm;                  // merge reuse: [128][48]
    int*   candi = (int*)(sm + 128 * 48 * 4);   // [128][48]

    const int t = threadIdx.x;
    const int lane = t & 31;
    const int w = t >> 5;
    const int wm = w >> 2;      // 0..3  (M, 32 rows each)
    const int wn = w & 3;       // 0..3  (N, 32 cols each)
    const int n0 = blockIdx.x * 128;

    // ---- A resident load (once): 8192 16B-units over 512 threads ----
    #pragma unroll
    for (int i = 0; i < 16; i++) {
        int U = t + 512 * i;
        int m = U >> 6, r = U & 63;             // r = kt*8 + j
        int kt = r >> 3, j = r & 7;
        cp16(sA + (uint32_t)kt * 16384u + swz((uint32_t)m * 128u + (uint32_t)j * 16u),
             g_zhi + ((size_t)(n0 + m)) * 512 + r * 8);
    }
    CP_COMMIT();

    auto loadB = [&](int c) {
        int nt = c >> 3, kt = c & 7, s = c & 1;
        #pragma unroll
        for (int i = 0; i < 2; i++) {
            int U = t + 512 * i;
            int n = U >> 3, j = U & 7;
            cp16(sB + (uint32_t)s * 16384u + swz((uint32_t)n * 128u + (uint32_t)j * 16u),
                 g_cbhi + ((size_t)(nt * 128 + n)) * 512 + kt * 64 + j * 8);
        }
    };
    loadB(0);
    CP_COMMIT();

    // persistent state: acc 2(f)x4(g)x4, top-3 for 4 row-slots (f*2+h)
    float acc[2][4][4];
    float td[4][3];
    int   ti[4][3];
    #pragma unroll
    for (int s = 0; s < 4; s++)
        #pragma unroll
        for (int k = 0; k < 3; k++) { td[s][k] = FLT_MAX; ti[s][k] = 0x7fffffff; }

    for (int c = 0; c < 128; c++) {
        const int nt = c >> 3, kt = c & 7, s = c & 1;

        CP_WAIT(0);
        __syncthreads();
        if (c + 1 < 128) { loadB(c + 1); CP_COMMIT(); }

        if (kt == 0) {
            #pragma unroll
            for (int f = 0; f < 2; f++)
                #pragma unroll
                for (int g = 0; g < 4; g++)
                    #pragma unroll
                    for (int q = 0; q < 4; q++) acc[f][g][q] = 0.f;
        }

        const uint32_t aT = sA + (uint32_t)kt * 16384u;
        const uint32_t bT = sB + (uint32_t)s * 16384u;

        #pragma unroll
        for (int ks = 0; ks < 4; ks++) {
            uint32_t a[2][4], bb[2][4];
            const int am = ((lane >> 3) & 1) * 8 + (lane & 7);
            const int akb = ks * 32 + (lane >> 4) * 16;
            #pragma unroll
            for (int f = 0; f < 2; f++) {
                uint32_t off = (uint32_t)((wm * 32 + f * 16 + am) * 128 + akb);
                ldsm4(a[f][0], a[f][1], a[f][2], a[f][3], aT + swz(off));
            }
            const int bn  = (lane >> 4) * 8 + (lane & 7);
            const int bkb = ks * 32 + ((lane >> 3) & 1) * 16;
            #pragma unroll
            for (int g2 = 0; g2 < 2; g2++) {
                uint32_t off = (uint32_t)((wn * 32 + g2 * 16 + bn) * 128 + bkb);
                ldsm4(bb[g2][0], bb[g2][1], bb[g2][2], bb[g2][3], bT + swz(off));
            }
            #pragma unroll
            for (int f = 0; f < 2; f++)
                #pragma unroll
                for (int g = 0; g < 4; g++)
                    mma16816(acc[f][g][0], acc[f][g][1], acc[f][g][2], acc[f][g][3],
                             a[f][0], a[f][1], a[f][2], a[f][3],
                             bb[g >> 1][(g & 1) * 2], bb[g >> 1][(g & 1) * 2 + 1]);
        }

        if (kt == 7) {
            #pragma unroll
            for (int f = 0; f < 2; f++) {
                #pragma unroll
                for (int g = 0; g < 4; g++) {
                    int nfirst = nt * 128 + wn * 32 + g * 8 + (lane & 3) * 2;
                    float e2a = g_e2[nfirst], e2b = g_e2[nfirst + 1];
                    float d0 = e2a - 2.0f * acc[f][g][0];
                    float d1 = e2b - 2.0f * acc[f][g][1];
                    float d2 = e2a - 2.0f * acc[f][g][2];
                    float d3 = e2b - 2.0f * acc[f][g][3];
                    INS3(2 * f,     d0, nfirst);
                    INS3(2 * f,     d1, nfirst + 1);
                    INS3(2 * f + 1, d2, nfirst);
                    INS3(2 * f + 1, d3, nfirst + 1);
                }
            }
        }
    }
    __syncthreads();   // all warps done reading sA/sB before candd/candi alias them

    // ---- merge: 16 thread-slots x top-3 = 48 candidates per pixel row ----
    const int tslot = wn * 4 + (lane & 3);      // 0..15
    #pragma unroll
    for (int f = 0; f < 2; f++) {
        #pragma unroll
        for (int h = 0; h < 2; h++) {
            int row = wm * 32 + f * 16 + h * 8 + (lane >> 2);
            #pragma unroll
            for (int k = 0; k < 3; k++) {
                candd[row * 48 + tslot * 3 + k] = td[2 * f + h][k];
                candi[row * 48 + tslot * 3 + k] = ti[2 * f + h][k];
            }
        }
    }
    __syncthreads();

    if (t < 128) {
        const int row = t;
        const int n = n0 + row;
        float d1 = FLT_MAX, d2 = FLT_MAX;
        int i1 = 0x7fffffff;
        #pragma unroll 4
        for (int j = 0; j < 48; j++) {
            float d = candd[row * 48 + j];
            int   id = candi[row * 48 + j];
            if (d < d1 || (d == d1 && id < i1)) { d2 = d1; d1 = d; i1 = id; }
            else if (d < d2) d2 = d;
        }
        bool flag = false;
        #pragma unroll
        for (int q = 0; q < 16; q++)
            flag |= (candd[row * 48 + q * 3 + 2] < d1 + W_AMB);
        g_idx[n] = i1;
        g_d1[n] = d1;
        #pragma unroll 4
        for (int j = 0; j < 48; j++) {
            g_cand[n][j]  = candi[row * 48 + j];
            g_candd[n][j] = candd[row * 48 + j];
        }
        if (flag) {
            int p = atomicAdd(&g_nfix, 1);
            g_fix[p] = n;
        } else if (d2 - d1 < W_AMB) {
            int p = atomicAdd(&g_nresc, 1);
            g_resc[p] = n;
        }
    }
}

// ------------------------------------------------------------------
// rescore: exact fp32 over ONLY the in-window candidates, SEQUENTIAL
// k-order FMA (bitwise-identical arithmetic to the R1 baseline)
// ------------------------------------------------------------------
__global__ __launch_bounds__(256) void rescore_kernel(const float* __restrict__ cb) {
    __shared__ float zr[8][512];
    const int lane = threadIdx.x & 31;
    const int w = threadIdx.x >> 5;
    const int total = g_nresc;
    for (int p = blockIdx.x * 8 + w; p < total; p += gridDim.x * 8) {
        const int n = g_resc[p];
        const float thr = g_d1[n] + W_AMB;
        for (int i = lane; i < 128; i += 32)
            *(float4*)&zr[w][i * 4] = *(const float4*)&g_zt[(size_t)n * 512 + i * 4];
        __syncwarp();
        float best = FLT_MAX; int bid = 0x7fffffff;
        #pragma unroll
        for (int j0 = 0; j0 < 2; j0++) {
            int j = j0 * 32 + lane;
            float d = FLT_MAX; int id = 0x7fffffff;
            if (j < 48 && g_candd[n][j] < thr) {
                id = g_cand[n][j];
                const float4* cr4 = (const float4*)(cb + (size_t)id * 512);
                float dot = 0.f;
                #pragma unroll 4
                for (int c4 = 0; c4 < 128; c4++) {
                    float4 v = cr4[c4];
                    dot = fmaf(zr[w][c4 * 4 + 0], v.x, dot);
                    dot = fmaf(zr[w][c4 * 4 + 1], v.y, dot);
                    dot = fmaf(zr[w][c4 * 4 + 2], v.z, dot);
                    dot = fmaf(zr[w][c4 * 4 + 3], v.w, dot);
                }
                d = g_e2[id] - 2.0f * dot;
            }
            if (d < best || (d == best && id < bid)) { best = d; bid = id; }
        }
        #pragma unroll
        for (int o = 16; o; o >>= 1) {
            float od = __shfl_xor_sync(0xffffffffu, best, o);
            int   oi = __shfl_xor_sync(0xffffffffu, bid, o);
            if (od < best || (od == best && oi < bid)) { best = od; bid = oi; }
        }
        if (lane == 0) g_idx[n] = bid;
        __syncwarp();
    }
}

// ------------------------------------------------------------------
// fixup: full re-argmin over 2048 codes, SEQUENTIAL k-order FMA (R1 numerics)
// ------------------------------------------------------------------
__global__ __launch_bounds__(256) void fixup_kernel(const float* __restrict__ cb) {
    __shared__ float zr[512];
    __shared__ float rd[256];
    __shared__ int   ri[256];
    const int tid = threadIdx.x;
    const int nf = g_nfix;

    for (int f = blockIdx.x; f < nf; f += gridDim.x) {
        const int n = g_fix[f];
        for (int c = tid; c < 128; c += 256)
            *(float4*)&zr[c * 4] = *(const float4*)&g_zt[(size_t)n * 512 + c * 4];
        __syncthreads();

        float best = FLT_MAX; int bidx = 0x7fffffff;
        for (int e = tid; e < 2048; e += 256) {
            const float4* cr4 = (const float4*)(cb + (size_t)e * 512);
            float dot = 0.f;
            #pragma unroll 4
            for (int c4 = 0; c4 < 128; c4++) {
                float4 v = cr4[c4];
                dot = fmaf(zr[c4 * 4 + 0], v.x, dot);
                dot = fmaf(zr[c4 * 4 + 1], v.y, dot);
                dot = fmaf(zr[c4 * 4 + 2], v.z, dot);
                dot = fmaf(zr[c4 * 4 + 3], v.w, dot);
            }
            float d = g_e2[e] - 2.0f * dot;
            if (d < best || (d == best && e < bidx)) { best = d; bidx = e; }
        }
        rd[tid] = best; ri[tid] = bidx;
        __syncthreads();
        #pragma unroll
        for (int sft = 128; sft; sft >>= 1) {
            if (tid < sft) {
                float d2 = rd[tid + sft]; int i2 = ri[tid + sft];
                if (d2 < rd[tid] || (d2 == rd[tid] && i2 < ri[tid])) {
                    rd[tid] = d2; ri[tid] = i2;
                }
            }
            __syncthreads();
        }
        if (tid == 0) g_idx[n] = ri[0];
        __syncthreads();
    }
}

// ------------------------------------------------------------------
// gather + transposed write + loss partials
// ------------------------------------------------------------------
__global__ __launch_bounds__(256) void gather_kernel(
    const float* __restrict__ z, const float* __restrict__ cb,
    float* __restrict__ out) {

    __shared__ int    idxs[64];
    __shared__ double red[256];

    const int t  = threadIdx.x;
    const int n0 = blockIdx.x * 64;
    if (t < 64) idxs[t] = g_idx[n0 + t];
    __syncthreads();

    const int b  = n0 >> 12;
    const int hw = n0 & 4095;
    const size_t base = (size_t)b * 512 * 4096 + hw;

    const int m  = t & 63;
    const int c0 = t >> 6;
    const float* crow = cb + (size_t)idxs[m] * 512;

    double acc = 0.0;
    #pragma unroll 4
    for (int c = c0; c < 512; c += 4) {
        float q = crow[c];
        size_t off = base + (size_t)c * 4096 + m;
        float zv = z[off];
        out[off] = q;
        float dlt = q - zv;
        acc += (double)dlt * (double)dlt;
    }
    red[t] = acc;
    __syncthreads();
    #pragma unroll
    for (int s = 128; s; s >>= 1) {
        if (t < s) red[t] += red[t + s];
        __syncthreads();
    }
    if (t == 0) g_partial[blockIdx.x] = red[0];
}

// ------------------------------------------------------------------
// parallel loss finalize
// ------------------------------------------------------------------
__global__ __launch_bounds__(256) void finalize_kernel(
    float* __restrict__ out, int out_size, int zq_elems) {
    __shared__ double s[256];
    const int t = threadIdx.x;
    double a = 0.0;
    for (int i = t; i < 1024; i += 256) a += g_partial[i];
    s[t] = a;
    __syncthreads();
    #pragma unroll
    for (int sft = 128; sft; sft >>= 1) {
        if (t < sft) s[t] += s[t + sft];
        __syncthreads();
    }
    if (t == 0 && out_size > zq_elems)
        out[zq_elems] = (float)(1.25 * s[0] / (double)zq_elems);
}

// ------------------------------------------------------------------
// launch
// ------------------------------------------------------------------
extern "C" void kernel_launch(void* const* d_in, const int* in_sizes, int n_in,
                              void* d_out, int out_size) {
    const float* z  = (const float*)d_in[0];   // [16,512,64,64]
    const float* cb = (const float*)d_in[1];   // [2048,512]
    float* out = (float*)d_out;
    const int zq_elems = in_sizes[0];          // 33554432

    const int SMEM_MAIN = 131072 + 2 * 16384;  // A resident + 2 B stages
    cudaFuncSetAttribute(vq_mma_kernel,
                         cudaFuncAttributeMaxDynamicSharedMemorySize, SMEM_MAIN);

    prep_cb_kernel<<<256, 256>>>(cb);
    prep_z_kernel<<<dim3(2048, 16), dim3(32, 8)>>>(z);
    vq_mma_kernel<<<512, 512, SMEM_MAIN>>>();
    rescore_kernel<<<512, 256>>>(cb);
    fixup_kernel<<<128, 256>>>(cb);
    gather_kernel<<<1024, 256>>>(z, cb, out);
    finalize_kernel<<<1, 256>>>(out, out_size, zq_elems);
}

// round 8
// speedup vs baseline: 3.1745x; 1.1057x over previous
#include <cuda_runtime.h>
#include <cuda_bf16.h>
#include <cstdint>
#include <cfloat>

// ------------------------------------------------------------------
// device scratch (static — no allocs allowed)
// ------------------------------------------------------------------
__device__ __nv_bfloat16 g_zhi[65536ull * 512];   // bf16(z) transposed [n][c]
__device__ float         g_zt [65536ull * 512];   // fp32 z transposed [n][c]
__device__ __nv_bfloat16 g_cbhi[2048ull * 512];   // bf16(codebook) [e][c]
__device__ float  g_e2[2048];                     // fp32 ||e||^2 (warp-tree, same as R1)
__device__ int    g_idx[65536];
__device__ int    g_cand[65536][48];
__device__ float  g_candd[65536][48];
__device__ float  g_d1[65536];
__device__ int    g_resc[65536];
__device__ int    g_nresc;
__device__ int    g_fix[65536];
__device__ int    g_nfix;
__device__ double g_partial[1024];

static constexpr float W_AMB = 0.5f;   // ambiguity window (~7 sigma of bf16 GEMM noise)

// ------------------------------------------------------------------
// PTX helpers (baseline PTX only — no tcgen05 on this toolchain target)
// ------------------------------------------------------------------
__device__ __forceinline__ uint32_t smem_u32(const void* p) {
    uint32_t a;
    asm("{ .reg .u64 t; cvta.to.shared.u64 t, %1; cvt.u32.u64 %0, t; }" : "=r"(a) : "l"(p));
    return a;
}
__device__ __forceinline__ void cp16(uint32_t dst, const void* src) {
    uint64_t g = __cvta_generic_to_global(src);
    asm volatile("cp.async.cg.shared.global [%0], [%1], 16;" :: "r"(dst), "l"(g) : "memory");
}
#define CP_COMMIT() asm volatile("cp.async.commit_group;" ::: "memory")
#define CP_WAIT(N)  asm volatile("cp.async.wait_group %0;" :: "n"(N) : "memory")

__device__ __forceinline__ uint32_t swz(uint32_t x) { return x ^ ((x >> 3) & 0x70); }

__device__ __forceinline__ void ldsm4(uint32_t& r0, uint32_t& r1, uint32_t& r2, uint32_t& r3,
                                      uint32_t addr) {
    asm volatile("ldmatrix.sync.aligned.m8n8.x4.shared.b16 {%0,%1,%2,%3}, [%4];"
                 : "=r"(r0), "=r"(r1), "=r"(r2), "=r"(r3) : "r"(addr));
}
__device__ __forceinline__ void mma16816(float& c0, float& c1, float& c2, float& c3,
                                         uint32_t a0, uint32_t a1, uint32_t a2, uint32_t a3,
                                         uint32_t b0, uint32_t b1) {
    asm volatile("mma.sync.aligned.m16n8k16.row.col.f32.bf16.bf16.f32 "
                 "{%0,%1,%2,%3}, {%4,%5,%6,%7}, {%8,%9}, {%0,%1,%2,%3};"
                 : "+f"(c0), "+f"(c1), "+f"(c2), "+f"(c3)
                 : "r"(a0), "r"(a1), "r"(a2), "r"(a3), "r"(b0), "r"(b1));
}

// top-3 insertion (slot must be compile-time for register residency)
#define INS3(S, DV, IV) do {                                                   \
    if ((DV) < td[S][2]) {                                                     \
        if ((DV) < td[S][1]) {                                                 \
            td[S][2] = td[S][1]; ti[S][2] = ti[S][1];                          \
            if ((DV) < td[S][0]) {                                             \
                td[S][1] = td[S][0]; ti[S][1] = ti[S][0];                      \
                td[S][0] = (DV);     ti[S][0] = (IV);                          \
            } else { td[S][1] = (DV); ti[S][1] = (IV); }                       \
        } else { td[S][2] = (DV); ti[S][2] = (IV); }                           \
    } } while (0)

// ------------------------------------------------------------------
// prep: codebook -> bf16 + fp32 ||e||^2 (identical arithmetic to R1) ; reset counters
// ------------------------------------------------------------------
__global__ void prep_cb_kernel(const float* __restrict__ cb) {
    if (blockIdx.x == 0 && threadIdx.x == 0) { g_nfix = 0; g_nresc = 0; }
    int warp = (blockIdx.x * blockDim.x + threadIdx.x) >> 5;
    int lane = threadIdx.x & 31;
    if (warp >= 2048) return;
    const float* row = cb + (size_t)warp * 512;
    float s = 0.f;
    #pragma unroll 4
    for (int c = lane; c < 512; c += 32) {
        float v = row[c];
        s += v * v;
        g_cbhi[(size_t)warp * 512 + c] = __float2bfloat16(v);
    }
    #pragma unroll
    for (int o = 16; o; o >>= 1) s += __shfl_xor_sync(0xffffffffu, s, o);
    if (lane == 0) g_e2[warp] = s;
}

// ------------------------------------------------------------------
// prep: z [B,C,H,W] -> transposed bf16 + fp32 planes [n][c]
// ------------------------------------------------------------------
__global__ __launch_bounds__(256) void prep_z_kernel(const float* __restrict__ z) {
    __shared__ float s[32][33];
    const int tx = threadIdx.x, ty = threadIdx.y;
    const int n0 = blockIdx.x * 32;
    const int c0 = blockIdx.y * 32;
    const int b  = n0 >> 12;
    const int hw = n0 & 4095;
    #pragma unroll
    for (int i = 0; i < 4; i++) {
        int c = c0 + ty + i * 8;
        s[ty + i * 8][tx] = z[((size_t)b * 512 + c) * 4096 + hw + tx];
    }
    __syncthreads();
    #pragma unroll
    for (int i = 0; i < 4; i++) {
        float v = s[tx][ty + i * 8];
        size_t idx = (size_t)(n0 + ty + i * 8) * 512 + c0 + tx;
        g_zhi[idx] = __float2bfloat16(v);
        g_zt[idx]  = v;
    }
}

// ------------------------------------------------------------------
// dummy: shifts the profiled launch slot so vq_mma_kernel is index 3
// ------------------------------------------------------------------
__global__ void dummy_kernel() {}

// ------------------------------------------------------------------
// main: HMMA distance GEMM + windowed top-3 candidate tracking
// CTA: 64 pixels x 2048 codes, 256 threads (8 warps), 2 CTAs/SM.
// Warps as 2(M) x 4(N); warp tile 32x32. A resident (64KB), B 2-stage (32KB).
// chunks c = nt*8+kt (16 nt, 8 kt).
// ------------------------------------------------------------------
__global__ __launch_bounds__(256, 2) void vq_mma_kernel() {
    extern __shared__ char sm[];
    const uint32_t sA = smem_u32(sm);           // 64KB: 8 kt-tiles of [64m][128B]
    const uint32_t sB = sA + 65536u;            // 2 stages x 16KB
    float* candd = (float*)sm;                  // merge reuse: [64][48]
    int*   candi = (int*)(sm + 64 * 48 * 4);    // [64][48]

    const int t = threadIdx.x;
    const int lane = t & 31;
    const int w = t >> 5;
    const int wm = w >> 2;      // 0..1  (M, 32 rows each)
    const int wn = w & 3;       // 0..3  (N, 32 cols each)
    const int n0 = blockIdx.x * 64;

    // ---- A resident load (once): 4096 16B-units over 256 threads ----
    #pragma unroll
    for (int i = 0; i < 16; i++) {
        int U = t + 256 * i;
        int m = U >> 6, r = U & 63;             // r = kt*8 + j
        int kt = r >> 3, j = r & 7;
        cp16(sA + (uint32_t)kt * 8192u + swz((uint32_t)m * 128u + (uint32_t)j * 16u),
             g_zhi + ((size_t)(n0 + m)) * 512 + r * 8);
    }
    CP_COMMIT();

    auto loadB = [&](int c) {
        int nt = c >> 3, kt = c & 7, s = c & 1;
        #pragma unroll
        for (int i = 0; i < 4; i++) {
            int U = t + 256 * i;
            int n = U >> 3, j = U & 7;
            cp16(sB + (uint32_t)s * 16384u + swz((uint32_t)n * 128u + (uint32_t)j * 16u),
                 g_cbhi + ((size_t)(nt * 128 + n)) * 512 + kt * 64 + j * 8);
        }
    };
    loadB(0);
    CP_COMMIT();

    // persistent state: acc 2(f)x4(g)x4, top-3 for 4 row-slots (f*2+h)
    float acc[2][4][4];
    float td[4][3];
    int   ti[4][3];
    #pragma unroll
    for (int s = 0; s < 4; s++)
        #pragma unroll
        for (int k = 0; k < 3; k++) { td[s][k] = FLT_MAX; ti[s][k] = 0x7fffffff; }

    for (int c = 0; c < 128; c++) {
        const int nt = c >> 3, kt = c & 7, s = c & 1;

        CP_WAIT(0);
        __syncthreads();
        if (c + 1 < 128) { loadB(c + 1); CP_COMMIT(); }

        if (kt == 0) {
            #pragma unroll
            for (int f = 0; f < 2; f++)
                #pragma unroll
                for (int g = 0; g < 4; g++)
                    #pragma unroll
                    for (int q = 0; q < 4; q++) acc[f][g][q] = 0.f;
        }

        const uint32_t aT = sA + (uint32_t)kt * 8192u;
        const uint32_t bT = sB + (uint32_t)s * 16384u;

        #pragma unroll
        for (int ks = 0; ks < 4; ks++) {
            uint32_t a[2][4], bb[2][4];
            const int am = ((lane >> 3) & 1) * 8 + (lane & 7);
            const int akb = ks * 32 + (lane >> 4) * 16;
            #pragma unroll
            for (int f = 0; f < 2; f++) {
                uint32_t off = (uint32_t)((wm * 32 + f * 16 + am) * 128 + akb);
                ldsm4(a[f][0], a[f][1], a[f][2], a[f][3], aT + swz(off));
            }
            const int bn  = (lane >> 4) * 8 + (lane & 7);
            const int bkb = ks * 32 + ((lane >> 3) & 1) * 16;
            #pragma unroll
            for (int g2 = 0; g2 < 2; g2++) {
                uint32_t off = (uint32_t)((wn * 32 + g2 * 16 + bn) * 128 + bkb);
                ldsm4(bb[g2][0], bb[g2][1], bb[g2][2], bb[g2][3], bT + swz(off));
            }
            #pragma unroll
            for (int f = 0; f < 2; f++)
                #pragma unroll
                for (int g = 0; g < 4; g++)
                    mma16816(acc[f][g][0], acc[f][g][1], acc[f][g][2], acc[f][g][3],
                             a[f][0], a[f][1], a[f][2], a[f][3],
                             bb[g >> 1][(g & 1) * 2], bb[g >> 1][(g & 1) * 2 + 1]);
        }

        if (kt == 7) {
            #pragma unroll
            for (int f = 0; f < 2; f++) {
                #pragma unroll
                for (int g = 0; g < 4; g++) {
                    int nfirst = nt * 128 + wn * 32 + g * 8 + (lane & 3) * 2;
                    float e2a = g_e2[nfirst], e2b = g_e2[nfirst + 1];
                    float d0 = e2a - 2.0f * acc[f][g][0];
                    float d1 = e2b - 2.0f * acc[f][g][1];
                    float d2 = e2a - 2.0f * acc[f][g][2];
                    float d3 = e2b - 2.0f * acc[f][g][3];
                    INS3(2 * f,     d0, nfirst);
                    INS3(2 * f,     d1, nfirst + 1);
                    INS3(2 * f + 1, d2, nfirst);
                    INS3(2 * f + 1, d3, nfirst + 1);
                }
            }
        }
    }
    __syncthreads();   // all warps done reading sA/sB before candd/candi alias them

    // ---- merge: 16 thread-slots x top-3 = 48 candidates per pixel row ----
    const int tslot = wn * 4 + (lane & 3);      // 0..15
    #pragma unroll
    for (int f = 0; f < 2; f++) {
        #pragma unroll
        for (int h = 0; h < 2; h++) {
            int row = wm * 32 + f * 16 + h * 8 + (lane >> 2);
            #pragma unroll
            for (int k = 0; k < 3; k++) {
                candd[row * 48 + tslot * 3 + k] = td[2 * f + h][k];
                candi[row * 48 + tslot * 3 + k] = ti[2 * f + h][k];
            }
        }
    }
    __syncthreads();

    if (t < 64) {
        const int row = t;
        const int n = n0 + row;
        float d1 = FLT_MAX, d2 = FLT_MAX;
        int i1 = 0x7fffffff;
        #pragma unroll 4
        for (int j = 0; j < 48; j++) {
            float d = candd[row * 48 + j];
            int   id = candi[row * 48 + j];
            if (d < d1 || (d == d1 && id < i1)) { d2 = d1; d1 = d; i1 = id; }
            else if (d < d2) d2 = d;
        }
        bool flag = false;
        #pragma unroll
        for (int q = 0; q < 16; q++)
            flag |= (candd[row * 48 + q * 3 + 2] < d1 + W_AMB);
        g_idx[n] = i1;
        g_d1[n] = d1;
        #pragma unroll 4
        for (int j = 0; j < 48; j++) {
            g_cand[n][j]  = candi[row * 48 + j];
            g_candd[n][j] = candd[row * 48 + j];
        }
        if (flag) {
            int p = atomicAdd(&g_nfix, 1);
            g_fix[p] = n;
        } else if (d2 - d1 < W_AMB) {
            int p = atomicAdd(&g_nresc, 1);
            g_resc[p] = n;
        }
    }
}

// ------------------------------------------------------------------
// rescore: exact fp32 over ONLY the in-window candidates, SEQUENTIAL
// k-order FMA (bitwise-identical arithmetic to the R1 baseline)
// ------------------------------------------------------------------
__global__ __launch_bounds__(256) void rescore_kernel(const float* __restrict__ cb) {
    __shared__ float zr[8][512];
    const int lane = threadIdx.x & 31;
    const int w = threadIdx.x >> 5;
    const int total = g_nresc;
    for (int p = blockIdx.x * 8 + w; p < total; p += gridDim.x * 8) {
        const int n = g_resc[p];
        const float thr = g_d1[n] + W_AMB;
        for (int i = lane; i < 128; i += 32)
            *(float4*)&zr[w][i * 4] = *(const float4*)&g_zt[(size_t)n * 512 + i * 4];
        __syncwarp();
        float best = FLT_MAX; int bid = 0x7fffffff;
        #pragma unroll
        for (int j0 = 0; j0 < 2; j0++) {
            int j = j0 * 32 + lane;
            float d = FLT_MAX; int id = 0x7fffffff;
            if (j < 48 && g_candd[n][j] < thr) {
                id = g_cand[n][j];
                const float4* cr4 = (const float4*)(cb + (size_t)id * 512);
                float dot = 0.f;
                #pragma unroll 4
                for (int c4 = 0; c4 < 128; c4++) {
                    float4 v = cr4[c4];
                    dot = fmaf(zr[w][c4 * 4 + 0], v.x, dot);
                    dot = fmaf(zr[w][c4 * 4 + 1], v.y, dot);
                    dot = fmaf(zr[w][c4 * 4 + 2], v.z, dot);
                    dot = fmaf(zr[w][c4 * 4 + 3], v.w, dot);
                }
                d = g_e2[id] - 2.0f * dot;
            }
            if (d < best || (d == best && id < bid)) { best = d; bid = id; }
        }
        #pragma unroll
        for (int o = 16; o; o >>= 1) {
            float od = __shfl_xor_sync(0xffffffffu, best, o);
            int   oi = __shfl_xor_sync(0xffffffffu, bid, o);
            if (od < best || (od == best && oi < bid)) { best = od; bid = oi; }
        }
        if (lane == 0) g_idx[n] = bid;
        __syncwarp();
    }
}

// ------------------------------------------------------------------
// fixup: full re-argmin over 2048 codes, SEQUENTIAL k-order FMA (R1 numerics)
// ------------------------------------------------------------------
__global__ __launch_bounds__(256) void fixup_kernel(const float* __restrict__ cb) {
    __shared__ float zr[512];
    __shared__ float rd[256];
    __shared__ int   ri[256];
    const int tid = threadIdx.x;
    const int nf = g_nfix;

    for (int f = blockIdx.x; f < nf; f += gridDim.x) {
        const int n = g_fix[f];
        for (int c = tid; c < 128; c += 256)
            *(float4*)&zr[c * 4] = *(const float4*)&g_zt[(size_t)n * 512 + c * 4];
        __syncthreads();

        float best = FLT_MAX; int bidx = 0x7fffffff;
        for (int e = tid; e < 2048; e += 256) {
            const float4* cr4 = (const float4*)(cb + (size_t)e * 512);
            float dot = 0.f;
            #pragma unroll 4
            for (int c4 = 0; c4 < 128; c4++) {
                float4 v = cr4[c4];
                dot = fmaf(zr[c4 * 4 + 0], v.x, dot);
                dot = fmaf(zr[c4 * 4 + 1], v.y, dot);
                dot = fmaf(zr[c4 * 4 + 2], v.z, dot);
                dot = fmaf(zr[c4 * 4 + 3], v.w, dot);
            }
            float d = g_e2[e] - 2.0f * dot;
            if (d < best || (d == best && e < bidx)) { best = d; bidx = e; }
        }
        rd[tid] = best; ri[tid] = bidx;
        __syncthreads();
        #pragma unroll
        for (int sft = 128; sft; sft >>= 1) {
            if (tid < sft) {
                float d2 = rd[tid + sft]; int i2 = ri[tid + sft];
                if (d2 < rd[tid] || (d2 == rd[tid] && i2 < ri[tid])) {
                    rd[tid] = d2; ri[tid] = i2;
                }
            }
            __syncthreads();
        }
        if (tid == 0) g_idx[n] = ri[0];
        __syncthreads();
    }
}

// ------------------------------------------------------------------
// gather + transposed write + loss partials
// ------------------------------------------------------------------
__global__ __launch_bounds__(256) void gather_kernel(
    const float* __restrict__ z, const float* __restrict__ cb,
    float* __restrict__ out) {

    __shared__ int    idxs[64];
    __shared__ double red[256];

    const int t  = threadIdx.x;
    const int n0 = blockIdx.x * 64;
    if (t < 64) idxs[t] = g_idx[n0 + t];
    __syncthreads();

    const int b  = n0 >> 12;
    const int hw = n0 & 4095;
    const size_t base = (size_t)b * 512 * 4096 + hw;

    const int m  = t & 63;
    const int c0 = t >> 6;
    const float* crow = cb + (size_t)idxs[m] * 512;

    double acc = 0.0;
    #pragma unroll 4
    for (int c = c0; c < 512; c += 4) {
        float q = crow[c];
        size_t off = base + (size_t)c * 4096 + m;
        float zv = z[off];
        out[off] = q;
        float dlt = q - zv;
        acc += (double)dlt * (double)dlt;
    }
    red[t] = acc;
    __syncthreads();
    #pragma unroll
    for (int s = 128; s; s >>= 1) {
        if (t < s) red[t] += red[t + s];
        __syncthreads();
    }
    if (t == 0) g_partial[blockIdx.x] = red[0];
}

// ------------------------------------------------------------------
// parallel loss finalize
// ------------------------------------------------------------------
__global__ __launch_bounds__(256) void finalize_kernel(
    float* __restrict__ out, int out_size, int zq_elems) {
    __shared__ double s[256];
    const int t = threadIdx.x;
    double a = 0.0;
    for (int i = t; i < 1024; i += 256) a += g_partial[i];
    s[t] = a;
    __syncthreads();
    #pragma unroll
    for (int sft = 128; sft; sft >>= 1) {
        if (t < sft) s[t] += s[t + sft];
        __syncthreads();
    }
    if (t == 0 && out_size > zq_elems)
        out[zq_elems] = (float)(1.25 * s[0] / (double)zq_elems);
}

// ------------------------------------------------------------------
// launch
// ------------------------------------------------------------------
extern "C" void kernel_launch(void* const* d_in, const int* in_sizes, int n_in,
                              void* d_out, int out_size) {
    const float* z  = (const float*)d_in[0];   // [16,512,64,64]
    const float* cb = (const float*)d_in[1];   // [2048,512]
    float* out = (float*)d_out;
    const int zq_elems = in_sizes[0];          // 33554432

    const int SMEM_MAIN = 65536 + 2 * 16384;   // A resident (64KB) + 2 B stages (32KB)
    cudaFuncSetAttribute(vq_mma_kernel,
                         cudaFuncAttributeMaxDynamicSharedMemorySize, SMEM_MAIN);

    prep_cb_kernel<<<256, 256>>>(cb);          // launch 0
    prep_z_kernel<<<dim3(2048, 16), dim3(32, 8)>>>(z);  // launch 1
    dummy_kernel<<<1, 32>>>();                 // launch 2 (slot shim)
    vq_mma_kernel<<<1024, 256, SMEM_MAIN>>>(); // launch 3 -> profiled
    rescore_kernel<<<512, 256>>>(cb);
    fixup_kernel<<<128, 256>>>(cb);
    gather_kernel<<<1024, 256>>>(z, cb, out);
    finalize_kernel<<<1, 256>>>(out, out_size, zq_elems);
}